// round 5
// baseline (speedup 1.0000x reference)
#include <cuda_runtime.h>

// SoftQuantize: x (8192,512) fp32, c (4,256) fp32, sigma (1,) fp32 -> out (8192,512) fp32
// rows = 8192*128 subvectors of dim 4; softmax over 256 centers.
//
// Exact ONLINE (flash) softmax, tiled by TT=4 centers: each dot product computed
// exactly once, cached in registers for the tile, then exp'd against the running
// max (accumulators rescaled by 2^(Mold-Mnew) once per tile).
// One row-PAIR per thread, f32x2-packed: each half-lane is a complete per-row
// value. Low register footprint -> 4 blocks/SM (32 warps) for latency hiding.
//
// arg_l = k1*(z.c_l) + beta_l, k1 = 2*s*log2e, beta_l = -s*log2e*||c_l||^2
// (z_sq dropped: softmax shift-invariant; running max keeps exp args <= 0).
// c pre-scaled by k1 (cancels in the ratio; undone by 1/k1 at the end).

#define LQ 256
#define TPB 256
#define G 2                 // rows per thread = 1 pair
#define TT 4                // center tile size
#define NROWS (8192*128)

typedef unsigned long long u64;

static __device__ __forceinline__ u64 pk(float lo, float hi) {
    u64 r; asm("mov.b64 %0, {%1, %2};" : "=l"(r) : "f"(lo), "f"(hi)); return r;
}
static __device__ __forceinline__ void unpk(u64 v, float& lo, float& hi) {
    asm("mov.b64 {%0, %1}, %2;" : "=f"(lo), "=f"(hi) : "l"(v));
}
static __device__ __forceinline__ u64 f2fma(u64 a, u64 b, u64 c) {
    u64 d; asm("fma.rn.f32x2 %0, %1, %2, %3;" : "=l"(d) : "l"(a), "l"(b), "l"(c)); return d;
}
static __device__ __forceinline__ u64 f2add(u64 a, u64 b) {
    u64 d; asm("add.rn.f32x2 %0, %1, %2;" : "=l"(d) : "l"(a), "l"(b)); return d;
}
static __device__ __forceinline__ u64 f2mul(u64 a, u64 b) {
    u64 d; asm("mul.rn.f32x2 %0, %1, %2;" : "=l"(d) : "l"(a), "l"(b)); return d;
}
static __device__ __forceinline__ float ex2f(float x) {
    float y; asm("ex2.approx.f32 %0, %1;" : "=f"(y) : "f"(x)); return y;
}
static __device__ __forceinline__ float rcpf(float x) {
    float y; asm("rcp.approx.f32 %0, %1;" : "=f"(y) : "f"(x)); return y;
}

__global__ __launch_bounds__(TPB, 4)
void softq_kernel(const float4* __restrict__ x4,
                  const float*  __restrict__ c,
                  const float*  __restrict__ sigma,
                  float4*       __restrict__ out4)
{
    __shared__ ulonglong2 scA[LQ];  // { pk(k1*c0,k1*c0), pk(k1*c1,k1*c1) }
    __shared__ ulonglong2 scB[LQ];  // { pk(k1*c2,k1*c2), pk(k1*c3,k1*c3) }
    __shared__ u64        sbb[LQ];  // pk(beta, beta)

    const float LOG2E = 1.4426950408889634f;
    float s  = fmaxf(sigma[0], 0.0f) + 1e-4f;
    float k1 = 2.0f * s * LOG2E;

    int t = threadIdx.x;            // t == center index for setup (TPB == LQ)
    {
        float c0 = c[t], c1 = c[LQ + t], c2 = c[2*LQ + t], c3 = c[3*LQ + t];
        float csq  = c0*c0 + c1*c1 + c2*c2 + c3*c3;
        float beta = -s * LOG2E * csq;
        scA[t].x = pk(k1*c0, k1*c0);
        scA[t].y = pk(k1*c1, k1*c1);
        scB[t].x = pk(k1*c2, k1*c2);
        scB[t].y = pk(k1*c3, k1*c3);
        sbb[t]   = pk(beta, beta);
    }
    __syncthreads();

    const int base = blockIdx.x * (TPB * G) + t;  // rows: base, base + TPB

    // zz[m]: component m of the two rows, packed
    u64 zz[4];
    {
        float4 a = x4[base];
        float4 b = x4[base + TPB];
        zz[0] = pk(a.x, b.x);
        zz[1] = pk(a.y, b.y);
        zz[2] = pk(a.z, b.z);
        zz[3] = pk(a.w, b.w);
    }

    float mLo = -1.0e30f, mHi = -1.0e30f;
    u64 negM = 0ull;                 // set per tile before use
    u64 den2 = 0ull;
    u64 nn0 = 0ull, nn1 = 0ull, nn2 = 0ull, nn3 = 0ull;

    #pragma unroll 1
    for (int tile = 0; tile < LQ; tile += TT) {
        // ---- phase 1: dots for the tile (cached) + scalar max tracking ----
        u64 aa[TT];
        float tLo = -1.0e30f, tHi = -1.0e30f;
        #pragma unroll
        for (int i = 0; i < TT; ++i) {
            int l = tile + i;
            ulonglong2 cA = scA[l];
            ulonglong2 cB = scB[l];
            u64 d = f2fma(zz[0], cA.x, sbb[l]);
            d     = f2fma(zz[1], cA.y, d);
            d     = f2fma(zz[2], cB.x, d);
            d     = f2fma(zz[3], cB.y, d);
            aa[i] = d;
            float lo, hi; unpk(d, lo, hi);
            tLo = fmaxf(tLo, lo);
            tHi = fmaxf(tHi, hi);
        }

        // ---- running-max update + accumulator rescale (once per tile) ----
        {
            float nmLo = fmaxf(mLo, tLo);
            float nmHi = fmaxf(mHi, tHi);
            float rLo = ex2f(mLo - nmLo);   // <= 1; 0 on first tile
            float rHi = ex2f(mHi - nmHi);
            mLo = nmLo; mHi = nmHi;
            negM = pk(-nmLo, -nmHi);
            u64 rr = pk(rLo, rHi);
            den2 = f2mul(den2, rr);
            nn0  = f2mul(nn0, rr);
            nn1  = f2mul(nn1, rr);
            nn2  = f2mul(nn2, rr);
            nn3  = f2mul(nn3, rr);
        }

        // ---- phase 2: exp from cached args + packed accumulation ----
        #pragma unroll
        for (int i = 0; i < TT; ++i) {
            int l = tile + i;
            ulonglong2 cA = scA[l];
            ulonglong2 cB = scB[l];
            u64 sa = f2add(aa[i], negM);    // arg - M <= 0
            float aL, aH; unpk(sa, aL, aH);
            u64 pp = pk(ex2f(aL), ex2f(aH));
            den2 = f2add(den2, pp);
            nn0  = f2fma(pp, cA.x, nn0);
            nn1  = f2fma(pp, cA.y, nn1);
            nn2  = f2fma(pp, cB.x, nn2);
            nn3  = f2fma(pp, cB.y, nn3);
        }
    }

    // ---- epilogue: divide, undo k1 scaling of c ----
    float invk1 = 1.0f / k1;
    {
        float dLo, dHi; unpk(den2, dLo, dHi);
        float sfLo = rcpf(dLo) * invk1;      // den >= 1 (max term == 1)
        float sfHi = rcpf(dHi) * invk1;
        float n0l, n0h, n1l, n1h, n2l, n2h, n3l, n3h;
        unpk(nn0, n0l, n0h);
        unpk(nn1, n1l, n1h);
        unpk(nn2, n2l, n2h);
        unpk(nn3, n3l, n3h);
        out4[base      ] = make_float4(n0l*sfLo, n1l*sfLo, n2l*sfLo, n3l*sfLo);
        out4[base + TPB] = make_float4(n0h*sfHi, n1h*sfHi, n2h*sfHi, n3h*sfHi);
    }
}

extern "C" void kernel_launch(void* const* d_in, const int* in_sizes, int n_in,
                              void* d_out, int out_size)
{
    const float* x     = (const float*)d_in[0];
    const float* c     = (const float*)d_in[1];
    const float* sigma = (const float*)d_in[2];
    float* out = (float*)d_out;

    int blocks = NROWS / (TPB * G);   // 2048
    softq_kernel<<<blocks, TPB>>>((const float4*)x, c, sigma, (float4*)out);
}

// round 6
// speedup vs baseline: 1.1967x; 1.1967x over previous
#include <cuda_runtime.h>

// SoftQuantize: x (8192,512) fp32, c (4,256) fp32, sigma (1,) fp32 -> out (8192,512) fp32
// rows = 8192*128 subvectors of dim 4; softmax over 256 centers.
//
// SINGLE PASS over centers using the full squared-distance form so every softmax
// argument is <= 0 (no max pass, each dot computed once, codebook LDS once):
//   arg_l = -s*log2e*||z-c_l||^2 = k1*(z.c_l) + beta_l + gamma_row
//   k1 = 2*s*log2e, beta_l = -s*log2e*||c_l||^2, gamma_row = -s*log2e*||z||^2
// For rare tail rows (huge ||z||) the denominator can underflow; those rows are
// detected (den < 1e-25) and recomputed exactly with a two-pass max fallback.
// With den >= 1e-25 the dominant term is a normal fp32, so accuracy is full.
//
// Row-pair f32x2 packing: each half-lane is a complete per-row value.
// c pre-scaled by k1 (cancels in the ratio; undone by 1/k1 at the end).

#define LQ 256
#define TPB 256
#define G 4                 // rows per thread = 2 pairs
#define NROWS (8192*128)
#define TINY 1e-25f

typedef unsigned long long u64;

static __device__ __forceinline__ u64 pk(float lo, float hi) {
    u64 r; asm("mov.b64 %0, {%1, %2};" : "=l"(r) : "f"(lo), "f"(hi)); return r;
}
static __device__ __forceinline__ void unpk(u64 v, float& lo, float& hi) {
    asm("mov.b64 {%0, %1}, %2;" : "=f"(lo), "=f"(hi) : "l"(v));
}
static __device__ __forceinline__ u64 f2fma(u64 a, u64 b, u64 c) {
    u64 d; asm("fma.rn.f32x2 %0, %1, %2, %3;" : "=l"(d) : "l"(a), "l"(b), "l"(c)); return d;
}
static __device__ __forceinline__ u64 f2add(u64 a, u64 b) {
    u64 d; asm("add.rn.f32x2 %0, %1, %2;" : "=l"(d) : "l"(a), "l"(b)); return d;
}
static __device__ __forceinline__ float ex2f(float x) {
    float y; asm("ex2.approx.f32 %0, %1;" : "=f"(y) : "f"(x)); return y;
}
static __device__ __forceinline__ float rcpf(float x) {
    float y; asm("rcp.approx.f32 %0, %1;" : "=f"(y) : "f"(x)); return y;
}

// Exact two-pass softmax for one row (rare tail fallback). Reads the packed
// codebook's low halves from shared memory.
static __device__ __noinline__ void fb_row(const float4* __restrict__ x4,
                                           float4* __restrict__ out4,
                                           int row,
                                           const ulonglong2* scA,
                                           const ulonglong2* scB,
                                           const u64* sbb,
                                           float invk1)
{
    float4 z = x4[row];
    float m = -1.0e30f;
    for (int l = 0; l < LQ; ++l) {
        const float* fA = (const float*)&scA[l];   // [0]=k1*c0, [2]=k1*c1
        const float* fB = (const float*)&scB[l];   // [0]=k1*c2, [2]=k1*c3
        float beta = ((const float*)&sbb[l])[0];
        float arg = fmaf(z.x, fA[0], beta);
        arg = fmaf(z.y, fA[2], arg);
        arg = fmaf(z.z, fB[0], arg);
        arg = fmaf(z.w, fB[2], arg);
        m = fmaxf(m, arg);
    }
    float den = 0.f, n0 = 0.f, n1 = 0.f, n2 = 0.f, n3 = 0.f;
    for (int l = 0; l < LQ; ++l) {
        const float* fA = (const float*)&scA[l];
        const float* fB = (const float*)&scB[l];
        float beta = ((const float*)&sbb[l])[0];
        float arg = fmaf(z.x, fA[0], beta);
        arg = fmaf(z.y, fA[2], arg);
        arg = fmaf(z.z, fB[0], arg);
        arg = fmaf(z.w, fB[2], arg);
        float p = ex2f(arg - m);
        den += p;
        n0 = fmaf(p, fA[0], n0);
        n1 = fmaf(p, fA[2], n1);
        n2 = fmaf(p, fB[0], n2);
        n3 = fmaf(p, fB[2], n3);
    }
    float sf = rcpf(den) * invk1;
    out4[row] = make_float4(n0*sf, n1*sf, n2*sf, n3*sf);
}

__global__ __launch_bounds__(TPB, 4)
void softq_kernel(const float4* __restrict__ x4,
                  const float*  __restrict__ c,
                  const float*  __restrict__ sigma,
                  float4*       __restrict__ out4)
{
    __shared__ ulonglong2 scA[LQ];  // { pk(k1*c0,k1*c0), pk(k1*c1,k1*c1) }
    __shared__ ulonglong2 scB[LQ];  // { pk(k1*c2,k1*c2), pk(k1*c3,k1*c3) }
    __shared__ u64        sbb[LQ];  // pk(beta, beta)

    const float LOG2E = 1.4426950408889634f;
    float s  = fmaxf(sigma[0], 0.0f) + 1e-4f;
    float sl = s * LOG2E;
    float k1 = 2.0f * sl;

    int t = threadIdx.x;            // t == center index for setup (TPB == LQ)
    {
        float c0 = c[t], c1 = c[LQ + t], c2 = c[2*LQ + t], c3 = c[3*LQ + t];
        float csq  = c0*c0 + c1*c1 + c2*c2 + c3*c3;
        float beta = -sl * csq;
        scA[t].x = pk(k1*c0, k1*c0);
        scA[t].y = pk(k1*c1, k1*c1);
        scB[t].x = pk(k1*c2, k1*c2);
        scB[t].y = pk(k1*c3, k1*c3);
        sbb[t]   = pk(beta, beta);
    }
    __syncthreads();

    const int base = blockIdx.x * (TPB * G) + t;  // rows: base + g*TPB, g=0..3

    // zz[m][p]: component m of rows (2p, 2p+1) packed; gg[p] = pk(-sl*||z||^2)
    u64 zz[4][2], gg[2];
    #pragma unroll
    for (int p = 0; p < 2; ++p) {
        float4 a = x4[base + (2*p    ) * TPB];
        float4 b = x4[base + (2*p + 1) * TPB];
        zz[0][p] = pk(a.x, b.x);
        zz[1][p] = pk(a.y, b.y);
        zz[2][p] = pk(a.z, b.z);
        zz[3][p] = pk(a.w, b.w);
        float za = a.x*a.x + a.y*a.y + a.z*a.z + a.w*a.w;
        float zb = b.x*b.x + b.y*b.y + b.z*b.z + b.w*b.w;
        gg[p] = pk(-sl * za, -sl * zb);
    }

    u64 den2[2] = {0ull, 0ull};
    u64 nn[4][2];
    nn[0][0] = nn[1][0] = nn[2][0] = nn[3][0] = 0ull;
    nn[0][1] = nn[1][1] = nn[2][1] = nn[3][1] = 0ull;

    #pragma unroll 2
    for (int l = 0; l < LQ; ++l) {
        ulonglong2 cA = scA[l];
        ulonglong2 cB = scB[l];
        u64 bb = sbb[l];
        #pragma unroll
        for (int p = 0; p < 2; ++p) {
            u64 d = f2fma(zz[0][p], cA.x, f2add(bb, gg[p]));
            d     = f2fma(zz[1][p], cA.y, d);
            d     = f2fma(zz[2][p], cB.x, d);
            d     = f2fma(zz[3][p], cB.y, d);
            float aL, aH; unpk(d, aL, aH);
            u64 pp = pk(ex2f(aL), ex2f(aH));     // args <= 0 -> (0,1]
            den2[p]  = f2add(den2[p], pp);
            nn[0][p] = f2fma(pp, cA.x, nn[0][p]);
            nn[1][p] = f2fma(pp, cA.y, nn[1][p]);
            nn[2][p] = f2fma(pp, cB.x, nn[2][p]);
            nn[3][p] = f2fma(pp, cB.y, nn[3][p]);
        }
    }

    // ---- epilogue: divide, undo k1 scaling; exact fallback for underflow ----
    float invk1 = 1.0f / k1;
    #pragma unroll
    for (int p = 0; p < 2; ++p) {
        float dLo, dHi; unpk(den2[p], dLo, dHi);
        int rowA = base + (2*p    ) * TPB;
        int rowB = base + (2*p + 1) * TPB;
        if (dLo < TINY || dHi < TINY) {
            fb_row(x4, out4, rowA, scA, scB, sbb, invk1);
            fb_row(x4, out4, rowB, scA, scB, sbb, invk1);
        } else {
            float sfLo = rcpf(dLo) * invk1;
            float sfHi = rcpf(dHi) * invk1;
            float n0l, n0h, n1l, n1h, n2l, n2h, n3l, n3h;
            unpk(nn[0][p], n0l, n0h);
            unpk(nn[1][p], n1l, n1h);
            unpk(nn[2][p], n2l, n2h);
            unpk(nn[3][p], n3l, n3h);
            out4[rowA] = make_float4(n0l*sfLo, n1l*sfLo, n2l*sfLo, n3l*sfLo);
            out4[rowB] = make_float4(n0h*sfHi, n1h*sfHi, n2h*sfHi, n3h*sfHi);
        }
    }
}

extern "C" void kernel_launch(void* const* d_in, const int* in_sizes, int n_in,
                              void* d_out, int out_size)
{
    const float* x     = (const float*)d_in[0];
    const float* c     = (const float*)d_in[1];
    const float* sigma = (const float*)d_in[2];
    float* out = (float*)d_out;

    int blocks = NROWS / (TPB * G);   // 1024
    softq_kernel<<<blocks, TPB>>>((const float4*)x, c, sigma, (float4*)out);
}

// round 7
// speedup vs baseline: 1.1999x; 1.0027x over previous
#include <cuda_runtime.h>

// SoftQuantize: x (8192,512) fp32, c (4,256) fp32, sigma (1,) fp32 -> out (8192,512) fp32
// rows = 8192*128 subvectors of dim 4; softmax over 256 centers.
//
// SINGLE PASS over centers using the full squared-distance form so every softmax
// argument is <= 0 (no max pass, each dot computed once, codebook LDS once):
//   arg_l = -s*log2e*||z-c_l||^2 = k1*(z.c_l) + gamma_row + beta_l
//   k1 = 2*s*log2e, beta_l = -s*log2e*||c_l||^2, gamma_row = -s*log2e*||z||^2
// Chain seeded with register-resident gamma; LDS-loaded beta appended LAST so
// the fma chain hides shared-memory latency. Codebook manually pipelined 2-wide.
// Rare tail rows (den underflow < 1e-25) are recomputed exactly (two-pass max).
//
// Row-pair f32x2 packing: each half-lane is a complete per-row value.
// c pre-scaled by k1 (cancels in the ratio; undone by 1/k1 at the end).

#define LQ 256
#define TPB 128
#define G 4                 // rows per thread = 2 pairs
#define NROWS (8192*128)
#define TINY 1e-25f

typedef unsigned long long u64;

static __device__ __forceinline__ u64 pk(float lo, float hi) {
    u64 r; asm("mov.b64 %0, {%1, %2};" : "=l"(r) : "f"(lo), "f"(hi)); return r;
}
static __device__ __forceinline__ void unpk(u64 v, float& lo, float& hi) {
    asm("mov.b64 {%0, %1}, %2;" : "=f"(lo), "=f"(hi) : "l"(v));
}
static __device__ __forceinline__ u64 f2fma(u64 a, u64 b, u64 c) {
    u64 d; asm("fma.rn.f32x2 %0, %1, %2, %3;" : "=l"(d) : "l"(a), "l"(b), "l"(c)); return d;
}
static __device__ __forceinline__ u64 f2add(u64 a, u64 b) {
    u64 d; asm("add.rn.f32x2 %0, %1, %2;" : "=l"(d) : "l"(a), "l"(b)); return d;
}
static __device__ __forceinline__ float ex2f(float x) {
    float y; asm("ex2.approx.f32 %0, %1;" : "=f"(y) : "f"(x)); return y;
}
static __device__ __forceinline__ float rcpf(float x) {
    float y; asm("rcp.approx.f32 %0, %1;" : "=f"(y) : "f"(x)); return y;
}

// Exact two-pass softmax for one row (rare tail fallback).
static __device__ __noinline__ void fb_row(const float4* __restrict__ x4,
                                           float4* __restrict__ out4,
                                           int row,
                                           const ulonglong2* scA,
                                           const ulonglong2* scB,
                                           const u64* sbb,
                                           float invk1)
{
    float4 z = x4[row];
    float m = -1.0e30f;
    for (int l = 0; l < LQ; ++l) {
        const float* fA = (const float*)&scA[l];   // [0]=k1*c0, [2]=k1*c1
        const float* fB = (const float*)&scB[l];   // [0]=k1*c2, [2]=k1*c3
        float beta = ((const float*)&sbb[l])[0];
        float arg = fmaf(z.x, fA[0], beta);
        arg = fmaf(z.y, fA[2], arg);
        arg = fmaf(z.z, fB[0], arg);
        arg = fmaf(z.w, fB[2], arg);
        m = fmaxf(m, arg);
    }
    float den = 0.f, n0 = 0.f, n1 = 0.f, n2 = 0.f, n3 = 0.f;
    for (int l = 0; l < LQ; ++l) {
        const float* fA = (const float*)&scA[l];
        const float* fB = (const float*)&scB[l];
        float beta = ((const float*)&sbb[l])[0];
        float arg = fmaf(z.x, fA[0], beta);
        arg = fmaf(z.y, fA[2], arg);
        arg = fmaf(z.z, fB[0], arg);
        arg = fmaf(z.w, fB[2], arg);
        float p = ex2f(arg - m);
        den += p;
        n0 = fmaf(p, fA[0], n0);
        n1 = fmaf(p, fA[2], n1);
        n2 = fmaf(p, fB[0], n2);
        n3 = fmaf(p, fB[2], n3);
    }
    float sf = rcpf(den) * invk1;
    out4[row] = make_float4(n0*sf, n1*sf, n2*sf, n3*sf);
}

__global__ __launch_bounds__(TPB, 8)
void softq_kernel(const float4* __restrict__ x4,
                  const float*  __restrict__ c,
                  const float*  __restrict__ sigma,
                  float4*       __restrict__ out4)
{
    __shared__ ulonglong2 scA[LQ];  // { pk(k1*c0,k1*c0), pk(k1*c1,k1*c1) }
    __shared__ ulonglong2 scB[LQ];  // { pk(k1*c2,k1*c2), pk(k1*c3,k1*c3) }
    __shared__ u64        sbb[LQ];  // pk(beta, beta)

    const float LOG2E = 1.4426950408889634f;
    float s  = fmaxf(sigma[0], 0.0f) + 1e-4f;
    float sl = s * LOG2E;
    float k1 = 2.0f * sl;

    int t = threadIdx.x;
    #pragma unroll
    for (int i = t; i < LQ; i += TPB) {
        float c0 = c[i], c1 = c[LQ + i], c2 = c[2*LQ + i], c3 = c[3*LQ + i];
        float csq  = c0*c0 + c1*c1 + c2*c2 + c3*c3;
        float beta = -sl * csq;
        scA[i].x = pk(k1*c0, k1*c0);
        scA[i].y = pk(k1*c1, k1*c1);
        scB[i].x = pk(k1*c2, k1*c2);
        scB[i].y = pk(k1*c3, k1*c3);
        sbb[i]   = pk(beta, beta);
    }
    __syncthreads();

    const int base = blockIdx.x * (TPB * G) + t;  // rows: base + g*TPB, g=0..3

    // zz[m][p]: component m of rows (2p, 2p+1) packed; gg[p] = pk(-sl*||z||^2)
    u64 zz[4][2], gg[2];
    #pragma unroll
    for (int p = 0; p < 2; ++p) {
        float4 a = x4[base + (2*p    ) * TPB];
        float4 b = x4[base + (2*p + 1) * TPB];
        zz[0][p] = pk(a.x, b.x);
        zz[1][p] = pk(a.y, b.y);
        zz[2][p] = pk(a.z, b.z);
        zz[3][p] = pk(a.w, b.w);
        float za = a.x*a.x + a.y*a.y + a.z*a.z + a.w*a.w;
        float zb = b.x*b.x + b.y*b.y + b.z*b.z + b.w*b.w;
        gg[p] = pk(-sl * za, -sl * zb);
    }

    u64 den2[2] = {0ull, 0ull};
    u64 nn[4][2];
    nn[0][0] = nn[1][0] = nn[2][0] = nn[3][0] = 0ull;
    nn[0][1] = nn[1][1] = nn[2][1] = nn[3][1] = 0ull;

    #pragma unroll 1
    for (int l = 0; l < LQ; l += 2) {
        // pipeline: pull both centers' codebook data up front
        ulonglong2 cA0 = scA[l],     cB0 = scB[l];
        ulonglong2 cA1 = scA[l + 1], cB1 = scB[l + 1];
        u64 bb0 = sbb[l], bb1 = sbb[l + 1];

        #pragma unroll
        for (int p = 0; p < 2; ++p) {
            // center l: seed with register gamma, append LDS beta last
            u64 d0 = f2fma(zz[0][p], cA0.x, gg[p]);
            d0     = f2fma(zz[1][p], cA0.y, d0);
            d0     = f2fma(zz[2][p], cB0.x, d0);
            d0     = f2fma(zz[3][p], cB0.y, d0);
            d0     = f2add(d0, bb0);
            float aL0, aH0; unpk(d0, aL0, aH0);
            u64 pp0 = pk(ex2f(aL0), ex2f(aH0));
            den2[p]  = f2add(den2[p], pp0);
            nn[0][p] = f2fma(pp0, cA0.x, nn[0][p]);
            nn[1][p] = f2fma(pp0, cA0.y, nn[1][p]);
            nn[2][p] = f2fma(pp0, cB0.x, nn[2][p]);
            nn[3][p] = f2fma(pp0, cB0.y, nn[3][p]);

            // center l+1
            u64 d1 = f2fma(zz[0][p], cA1.x, gg[p]);
            d1     = f2fma(zz[1][p], cA1.y, d1);
            d1     = f2fma(zz[2][p], cB1.x, d1);
            d1     = f2fma(zz[3][p], cB1.y, d1);
            d1     = f2add(d1, bb1);
            float aL1, aH1; unpk(d1, aL1, aH1);
            u64 pp1 = pk(ex2f(aL1), ex2f(aH1));
            den2[p]  = f2add(den2[p], pp1);
            nn[0][p] = f2fma(pp1, cA1.x, nn[0][p]);
            nn[1][p] = f2fma(pp1, cA1.y, nn[1][p]);
            nn[2][p] = f2fma(pp1, cB1.x, nn[2][p]);
            nn[3][p] = f2fma(pp1, cB1.y, nn[3][p]);
        }
    }

    // ---- epilogue: divide, undo k1 scaling; exact fallback for underflow ----
    float invk1 = 1.0f / k1;
    #pragma unroll
    for (int p = 0; p < 2; ++p) {
        float dLo, dHi; unpk(den2[p], dLo, dHi);
        int rowA = base + (2*p    ) * TPB;
        int rowB = base + (2*p + 1) * TPB;
        if (dLo < TINY || dHi < TINY) {
            fb_row(x4, out4, rowA, scA, scB, sbb, invk1);
            fb_row(x4, out4, rowB, scA, scB, sbb, invk1);
        } else {
            float sfLo = rcpf(dLo) * invk1;
            float sfHi = rcpf(dHi) * invk1;
            float n0l, n0h, n1l, n1h, n2l, n2h, n3l, n3h;
            unpk(nn[0][p], n0l, n0h);
            unpk(nn[1][p], n1l, n1h);
            unpk(nn[2][p], n2l, n2h);
            unpk(nn[3][p], n3l, n3h);
            out4[rowA] = make_float4(n0l*sfLo, n1l*sfLo, n2l*sfLo, n3l*sfLo);
            out4[rowB] = make_float4(n0h*sfHi, n1h*sfHi, n2h*sfHi, n3h*sfHi);
        }
    }
}

extern "C" void kernel_launch(void* const* d_in, const int* in_sizes, int n_in,
                              void* d_out, int out_size)
{
    const float* x     = (const float*)d_in[0];
    const float* c     = (const float*)d_in[1];
    const float* sigma = (const float*)d_in[2];
    float* out = (float*)d_out;

    int blocks = NROWS / (TPB * G);   // 2048
    softq_kernel<<<blocks, TPB>>>((const float4*)x, c, sigma, (float4*)out);
}